// round 16
// baseline (speedup 1.0000x reference)
#include <cuda_runtime.h>
#include <math.h>
#include <stdint.h>
#include <cuda_fp16.h>

// Problem dims (fixed by the dataset)
#define B_  2
#define N_  1024
#define C_  256
#define NQ_ 100
#define HALF_ 128

// Scratch (device globals: no allocation allowed)
__device__ __half g_Ah[B_ * N_ * C_];      // h_loc @ W1a (fp16)   (per b,t)
__device__ float  g_hg[B_ * N_ * HALF_];   // h glob half          (per b,t)
__device__ float  g_Cq[B_ * NQ_ * C_];     // q@W1c                (per b,i)
__device__ float  g_gt[B_ * C_];           // glob@W1b + b1        (per b)
__device__ __half g_W2h[HALF_ * C_];       // W2 transposed [j][k], fp16

// ---------------------------------------------------------------------------
// gelu, packed helpers (f32x2, sm_100+ PTX)
// ---------------------------------------------------------------------------
__device__ __forceinline__ uint64_t dup2_(float c) {
    uint64_t r; asm("mov.b64 %0, {%1, %1};" : "=l"(r) : "f"(c)); return r;
}
#define FMA2_(d, a, b, c) asm("fma.rn.f32x2 %0, %1, %2, %3;" : "=l"(d) : "l"(a), "l"(b), "l"(c))
#define MUL2_(d, a, b)    asm("mul.rn.f32x2 %0, %1, %2;"     : "=l"(d) : "l"(a), "l"(b))
#define ADD2_(d, a, b)    asm("add.rn.f32x2 %0, %1, %2;"     : "=l"(d) : "l"(a), "l"(b))

// Exact-precision path: A-S 7.1.26 erf (|err|<=1.5e-7), packed 2-wide.
__device__ __forceinline__ void gelu2_f(float xa, float xb, float& ra, float& rb) {
    uint64_t xp; asm("mov.b64 %0, {%1, %2};" : "=l"(xp) : "f"(xa), "f"(xb));
    const uint64_t ap = xp & 0x7FFFFFFF7FFFFFFFULL;
    uint64_t axk; MUL2_(axk, ap, dup2_(0.70710678118654752440f));
    uint64_t den; FMA2_(den, axk, dup2_(0.3275911f), dup2_(1.0f));
    float d0, d1; asm("mov.b64 {%0, %1}, %2;" : "=f"(d0), "=f"(d1) : "l"(den));
    float t0, t1;
    asm("rcp.approx.f32 %0, %1;" : "=f"(t0) : "f"(d0));
    asm("rcp.approx.f32 %0, %1;" : "=f"(t1) : "f"(d1));
    uint64_t t; asm("mov.b64 %0, {%1, %2};" : "=l"(t) : "f"(t0), "f"(t1));
    uint64_t p;
    FMA2_(p, dup2_(1.061405429f), t, dup2_(-1.453152027f));
    FMA2_(p, p, t, dup2_(1.421413741f));
    FMA2_(p, p, t, dup2_(-0.284496736f));
    FMA2_(p, p, t, dup2_(0.254829592f));
    MUL2_(p, p, t);
    uint64_t z2; MUL2_(z2, axk, axk);
    uint64_t w;  MUL2_(w, z2, dup2_(-1.4426950408889634f));   // -z^2 * log2(e)
    float w0, w1; asm("mov.b64 {%0, %1}, %2;" : "=f"(w0), "=f"(w1) : "l"(w));
    float e0, e1;
    asm("ex2.approx.f32 %0, %1;" : "=f"(e0) : "f"(w0));
    asm("ex2.approx.f32 %0, %1;" : "=f"(e1) : "f"(w1));
    uint64_t e; asm("mov.b64 %0, {%1, %2};" : "=l"(e) : "f"(e0), "f"(e1));
    uint64_t pe; MUL2_(pe, p, e);
    uint64_t er; FMA2_(er, pe, dup2_(-1.0f), dup2_(1.0f));    // 1 - p*e = erf(ax)
    const uint64_t s = er | (xp & 0x8000000080000000ULL);     // copysign (er>0)
    uint64_t onep; ADD2_(onep, s, dup2_(1.0f));
    uint64_t hx;   MUL2_(hx, xp, dup2_(0.5f));
    uint64_t res;  MUL2_(res, onep, hx);
    asm("mov.b64 {%0, %1}, %2;" : "=f"(ra), "=f"(rb) : "l"(res));
}

__device__ __forceinline__ uint32_t f2h2(float a, float b) {
    __half2 h = __floats2half2_rn(a, b);
    return *reinterpret_cast<uint32_t*>(&h);
}

// Fast path: tanh-form gelu with HW tanh.approx (floats out).
__device__ __forceinline__ void gelu2t_f(float xa, float xb, float& ra, float& rb) {
    uint64_t xp; asm("mov.b64 %0, {%1, %2};" : "=l"(xp) : "f"(xa), "f"(xb));
    uint64_t z2; MUL2_(z2, xp, xp);
    uint64_t cc; FMA2_(cc, z2, dup2_(0.0356774081f), dup2_(0.7978845608f));
    uint64_t in; MUL2_(in, xp, cc);
    float i0, i1; asm("mov.b64 {%0, %1}, %2;" : "=f"(i0), "=f"(i1) : "l"(in));
    float t0, t1;
    asm("tanh.approx.f32 %0, %1;" : "=f"(t0) : "f"(i0));
    asm("tanh.approx.f32 %0, %1;" : "=f"(t1) : "f"(i1));
    uint64_t tp; asm("mov.b64 %0, {%1, %2};" : "=l"(tp) : "f"(t0), "f"(t1));
    uint64_t hf; FMA2_(hf, tp, dup2_(0.5f), dup2_(0.5f));
    uint64_t res; MUL2_(res, xp, hf);
    asm("mov.b64 {%0, %1}, %2;" : "=f"(ra), "=f"(rb) : "l"(res));
}

__device__ __forceinline__ uint32_t gelu2t_h2(float xa, float xb) {
    float ra, rb;
    gelu2t_f(xa, xb, ra, rb);
    return f2h2(ra, rb);
}

__device__ __forceinline__ void mma_f16(float* d, const uint32_t* a, const uint32_t* b) {
    asm volatile(
        "mma.sync.aligned.m16n8k16.row.col.f32.f16.f16.f32 "
        "{%0,%1,%2,%3}, {%4,%5,%6,%7}, {%8,%9}, {%0,%1,%2,%3};"
        : "+f"(d[0]), "+f"(d[1]), "+f"(d[2]), "+f"(d[3])
        : "r"(a[0]), "r"(a[1]), "r"(a[2]), "r"(a[3]), "r"(b[0]), "r"(b[1]));
}

// ---------------------------------------------------------------------------
// K1 (merged): blocks 0..255   : h = gelu(LN(x)@W_in+b_in); A_loc = h_loc@W1a
//              blocks 256..455 : Cq[b,i,:] = query[i,b,:] @ W1[256:512]
// 1024 threads, 4-way split-K: thread = (col, kq).
// ---------------------------------------------------------------------------
__global__ void __launch_bounds__(1024) k1_ln_gemm_gelu(
    const float* __restrict__ x, const float* __restrict__ ln_g,
    const float* __restrict__ ln_b, const float* __restrict__ Win,
    const float* __restrict__ bin, const float* __restrict__ W1,
    const float* __restrict__ query)
{
    const int blk = blockIdx.x;
    const int tid = threadIdx.x;
    const int col = tid & 255;
    const int kq  = tid >> 8;            // 0..3

    if (blk >= 256) {
        // ---- query GEMM: one CTA per (b,i) ----
        __shared__ float sQ[C_];
        __shared__ float pq[3][C_];
        const int bi = blk - 256;
        const int b = bi / NQ_, i = bi % NQ_;
        if (tid < C_) sQ[tid] = query[(i * B_ + b) * C_ + tid];
        __syncthreads();

        float a[8];
        #pragma unroll
        for (int u = 0; u < 8; u++) a[u] = 0.f;
        const int kb = kq * 64;
        #pragma unroll 2
        for (int k = kb; k < kb + 64; k += 8) {
            #pragma unroll
            for (int u = 0; u < 8; u++)
                a[u] += sQ[k + u] * W1[(C_ + k + u) * C_ + col];
        }
        const float sum =
            ((a[0] + a[1]) + (a[2] + a[3])) + ((a[4] + a[5]) + (a[6] + a[7]));
        if (kq > 0) pq[kq - 1][col] = sum;
        __syncthreads();
        if (kq == 0)
            g_Cq[bi * C_ + col] = sum + pq[0][col] + pq[1][col] + pq[2][col];
        return;
    }

    __shared__ __align__(16) float sY[8][C_];
    __shared__ float pp[3][8][C_];
    __shared__ float sred[8][8][2];
    __shared__ float smu[8], ssc[8];

    const int lane = tid & 31;
    const int wid  = tid >> 5;           // 0..31
    const int row0 = blk * 8;

    const float gv = ln_g[col];
    const float bv = ln_b[col];

    // --- stats: quarter kq owns rows kq*2, kq*2+1 ---
    const int rbase = kq * 2;
    float xv[2];
    #pragma unroll
    for (int r = 0; r < 2; r++)
        xv[r] = x[(row0 + rbase + r) * C_ + col];

    {
        const int w8 = wid & 7;
        #pragma unroll
        for (int r = 0; r < 2; r++) {
            float s = xv[r], q = xv[r] * xv[r];
            #pragma unroll
            for (int o = 16; o; o >>= 1) {
                s += __shfl_xor_sync(0xffffffffu, s, o);
                q += __shfl_xor_sync(0xffffffffu, q, o);
            }
            if (lane == 0) { sred[rbase + r][w8][0] = s; sred[rbase + r][w8][1] = q; }
        }
    }
    __syncthreads();
    if (wid < 8) {
        float s = (lane < 8) ? sred[wid][lane][0] : 0.f;
        float q = (lane < 8) ? sred[wid][lane][1] : 0.f;
        #pragma unroll
        for (int o = 4; o; o >>= 1) {
            s += __shfl_xor_sync(0xffffffffu, s, o);
            q += __shfl_xor_sync(0xffffffffu, q, o);
        }
        if (lane == 0) {
            const float mu = s * (1.0f / C_);
            const float var = q * (1.0f / C_) - mu * mu;
            smu[wid] = mu;
            ssc[wid] = rsqrtf(var + 1e-5f);
        }
    }
    __syncthreads();
    #pragma unroll
    for (int r = 0; r < 2; r++)
        sY[rbase + r][col] = (xv[r] - smu[rbase + r]) * ssc[rbase + r] * gv + bv;
    __syncthreads();

    // --- GEMM1: y @ W_in, K=256 split 64/64/64/64 across kq ---
    float acc[8];
    #pragma unroll
    for (int r = 0; r < 8; r++) acc[r] = 0.f;
    {
        const int kb = kq * 64;
        for (int k = kb; k < kb + 64; k += 4) {
            const float w0 = Win[(k + 0) * C_ + col];
            const float w1 = Win[(k + 1) * C_ + col];
            const float w2 = Win[(k + 2) * C_ + col];
            const float w3 = Win[(k + 3) * C_ + col];
            #pragma unroll
            for (int r = 0; r < 8; r++) {
                const float4 y = *(const float4*)&sY[r][k];
                acc[r] += y.x * w0 + y.y * w1 + y.z * w2 + y.w * w3;
            }
        }
    }
    if (kq > 0) {
        #pragma unroll
        for (int r = 0; r < 8; r++) pp[kq - 1][r][col] = acc[r];
    }
    __syncthreads();

    if (kq == 0) {
        const float bi0 = bin[col];
        float hr[8];
        #pragma unroll
        for (int r = 0; r < 8; r += 2) {
            const float s0 = acc[r] + pp[0][r][col] + pp[1][r][col] + pp[2][r][col] + bi0;
            const float s1 = acc[r + 1] + pp[0][r + 1][col] + pp[1][r + 1][col] + pp[2][r + 1][col] + bi0;
            gelu2_f(s0, s1, hr[r], hr[r + 1]);
        }
        if (col < HALF_) {
            #pragma unroll
            for (int r = 0; r < 8; r++) sY[r][col] = hr[r];
        } else {
            #pragma unroll
            for (int r = 0; r < 8; r++)
                g_hg[(row0 + r) * HALF_ + col - HALF_] = hr[r];
        }
    }
    __syncthreads();

    // --- GEMM2: h_loc @ W1[0:128], K=128 split 32x4 across kq ---
    float a2[8];
    #pragma unroll
    for (int r = 0; r < 8; r++) a2[r] = 0.f;
    {
        const int kb = kq * 32;
        for (int k = kb; k < kb + 32; k += 4) {
            const float w0 = W1[(k + 0) * C_ + col];
            const float w1 = W1[(k + 1) * C_ + col];
            const float w2 = W1[(k + 2) * C_ + col];
            const float w3 = W1[(k + 3) * C_ + col];
            #pragma unroll
            for (int r = 0; r < 8; r++) {
                const float4 y = *(const float4*)&sY[r][k];
                a2[r] += y.x * w0 + y.y * w1 + y.z * w2 + y.w * w3;
            }
        }
    }
    if (kq > 0) {
        #pragma unroll
        for (int r = 0; r < 8; r++) pp[kq - 1][r][col] = a2[r];
    }
    __syncthreads();
    if (kq == 0) {
        #pragma unroll
        for (int r = 0; r < 8; r++)
            g_Ah[(row0 + r) * C_ + col] =
                __float2half_rn(a2[r] + pp[0][r][col] + pp[1][r][col] + pp[2][r][col]);
    }
}

// ---------------------------------------------------------------------------
// K23: remaining prologue.  grid = 18 CTAs x 512 thr.
//   blocks 0..1   : glob + gt (needs g_hg from k1)
//   blocks 2..17  : W2h transpose to fp16
// ---------------------------------------------------------------------------
__global__ void __launch_bounds__(512) k23_pre(
    const float* __restrict__ W1, const float* __restrict__ policy,
    const float* __restrict__ b1, const float* __restrict__ W2)
{
    const int blk = blockIdx.x;
    const int tid = threadIdx.x;

    if (blk < 2) {
        const int b = blk;
        const int lane = tid & 31, wid = tid >> 5;
        __shared__ float spol[N_];
        __shared__ float sred[16];
        __shared__ float sps;
        __shared__ float sG[4][HALF_];
        __shared__ float sglob[HALF_];

        float ps = 0.f;
        #pragma unroll
        for (int i = 0; i < 2; i++) {
            const float p = policy[b * N_ + tid + i * 512];
            spol[tid + i * 512] = p;
            ps += p;
        }
        #pragma unroll
        for (int o = 16; o; o >>= 1) ps += __shfl_xor_sync(0xffffffffu, ps, o);
        if (lane == 0) sred[wid] = ps;
        __syncthreads();

        const int c = tid & 127, sl = tid >> 7;     // 4 slices of 256 t
        float acc = 0.f;
        for (int t = sl * 256; t < sl * 256 + 256; t++)
            acc += g_hg[(b * N_ + t) * HALF_ + c] * spol[t];
        sG[sl][c] = acc;
        if (tid == 0) {
            float s = 0.f;
            #pragma unroll
            for (int w = 0; w < 16; w++) s += sred[w];
            sps = s;
        }
        __syncthreads();
        if (tid < HALF_)
            sglob[tid] = (sG[0][tid] + sG[1][tid] + sG[2][tid] + sG[3][tid]) / sps;
        __syncthreads();

        if (tid < C_) {
            float g = b1[tid];
            for (int k = 0; k < HALF_; k++)
                g += sglob[k] * W1[(HALF_ + k) * C_ + tid];
            g_gt[b * C_ + tid] = g;
        }
    } else {
        const int base = (blk - 2) * 2048;
        #pragma unroll
        for (int i = 0; i < 4; i++) {
            const int lin = base + i * 512 + tid;   // index into W2 [k][j]
            const int k = lin >> 7, j = lin & 127;
            g_W2h[j * C_ + k] = __float2half_rn(W2[lin]);
        }
    }
}

// ---------------------------------------------------------------------------
// K4: fused  u = gelu(Aloc[b,t]+Cq[b,i]+gt[b]) ; v = gelu(u@W2+b2) ;
//            w = v@W3+b3 ; out = log_softmax(w)
// fp16 mma.sync m16n8k16, fp32 accum. Double-buffered K-chunks of 64.
// grid (8, 200), 512 threads = 16 warps (4x4 warp grid, 32x32 warp tile).
// 2 CTAs/SM -> 32 warps/SM for latency hiding.
// ---------------------------------------------------------------------------
#define KC  64                 // K elements per chunk
#define US  72                 // smem row stride in halves (pad 8)
#define UBUF (128 * US)        // halves per buffer

__global__ void __launch_bounds__(512, 2) k4_h16(
    const float* __restrict__ b2v,
    const float* __restrict__ W3, const float* __restrict__ b3,
    float* __restrict__ out)
{
    extern __shared__ __half dynh[];
    __half* sU = dynh;                  // [2][128*US] gelu tile (fp16)
    __half* sW = dynh + 2 * UBUF;       // [2][128*US] W2 chunk  (fp16)

    __shared__ __align__(16) float sC[C_];
    __shared__ float sB2[HALF_];
    __shared__ float sW3[2 * HALF_];
    __shared__ float sPW[4][HALF_][2];

    const int tid = threadIdx.x;
    const int lane = tid & 31, warp = tid >> 5;   // warp 0..15
    const int wm = warp >> 2, wn = warp & 3;      // 4x4 warp grid
    const int g = lane >> 2, tig = lane & 3;

    const int bi = blockIdx.y;            // b*100 + i
    const int b = bi / NQ_;
    const int t0 = blockIdx.x * 128;
    const __half* aBase = g_Ah + (b * N_ + t0) * C_;

    if (tid < C_) sC[tid] = g_Cq[bi * C_ + tid] + g_gt[b * C_ + tid];
    if (tid < HALF_) sB2[tid] = b2v[tid];
    if (tid < 2 * HALF_) sW3[tid] = W3[tid];

    float acc[2][4][4];
    #pragma unroll
    for (int mi = 0; mi < 2; mi++)
        #pragma unroll
        for (int ni = 0; ni < 4; ni++)
            #pragma unroll
            for (int q = 0; q < 4; q++) acc[mi][ni][q] = 0.f;
    __syncthreads();   // sC ready before first fill

    // Fill coords: each thread does 2 uint4 (rows ft, groups fq, fq+1)
    const int ft = tid >> 2;             // 0..127
    const int fq = (tid & 3) * 2;        // 0,2,4,6

    // fill chunk 0 into buffer 0
    {
        __half* uDst = sU + ft * US;
        #pragma unroll
        for (int i = 0; i < 2; i++) {
            const int q = fq + i;
            const uint4 a4 = *(const uint4*)(aBase + ft * C_ + q * 8);
            const float2 a0 = __half22float2(*(const __half2*)&a4.x);
            const float2 a1 = __half22float2(*(const __half2*)&a4.y);
            const float2 a2 = __half22float2(*(const __half2*)&a4.z);
            const float2 a3 = __half22float2(*(const __half2*)&a4.w);
            const float4 c0 = *(const float4*)(sC + q * 8);
            const float4 c1 = *(const float4*)(sC + q * 8 + 4);
            uint4 u;
            u.x = gelu2t_h2(a0.x + c0.x, a0.y + c0.y);
            u.y = gelu2t_h2(a1.x + c0.z, a1.y + c0.w);
            u.z = gelu2t_h2(a2.x + c1.x, a2.y + c1.y);
            u.w = gelu2t_h2(a3.x + c1.z, a3.y + c1.w);
            *(uint4*)(uDst + q * 8) = u;
        }
        #pragma unroll
        for (int i = 0; i < 2; i++) {
            const int e = tid + i * 512;
            const int j = e >> 3, q = e & 7;
            *(uint4*)(sW + j * US + q * 8) =
                *(const uint4*)(g_W2h + j * C_ + q * 8);
        }
    }
    __syncthreads();

    for (int c = 0; c < 4; c++) {
        const __half* bU = sU + (c & 1) * UBUF;
        const __half* bW = sW + (c & 1) * UBUF;

        #pragma unroll
        for (int ks = 0; ks < KC; ks += 16) {
            uint32_t af[2][4], bf[4][2];
            #pragma unroll
            for (int mi = 0; mi < 2; mi++) {
                const int row = wm * 32 + mi * 16 + g;
                af[mi][0] = *(const uint32_t*)(bU + row * US + ks + 2 * tig);
                af[mi][1] = *(const uint32_t*)(bU + (row + 8) * US + ks + 2 * tig);
                af[mi][2] = *(const uint32_t*)(bU + row * US + ks + 2 * tig + 8);
                af[mi][3] = *(const uint32_t*)(bU + (row + 8) * US + ks + 2 * tig + 8);
            }
            #pragma unroll
            for (int ni = 0; ni < 4; ni++) {
                const int j = wn * 32 + ni * 8 + g;
                bf[ni][0] = *(const uint32_t*)(bW + j * US + ks + 2 * tig);
                bf[ni][1] = *(const uint32_t*)(bW + j * US + ks + 2 * tig + 8);
            }
            #pragma unroll
            for (int mi = 0; mi < 2; mi++)
                #pragma unroll
                for (int ni = 0; ni < 4; ni++)
                    mma_f16(acc[mi][ni], af[mi], bf[ni]);
        }

        if (c < 3) {
            const int k0 = (c + 1) * KC;
            __half* uDst = sU + ((c + 1) & 1) * UBUF + ft * US;
            __half* wDst = sW + ((c + 1) & 1) * UBUF;
            #pragma unroll
            for (int i = 0; i < 2; i++) {
                const int q = fq + i;
                const uint4 a4 = *(const uint4*)(aBase + ft * C_ + k0 + q * 8);
                const float2 a0 = __half22float2(*(const __half2*)&a4.x);
                const float2 a1 = __half22float2(*(const __half2*)&a4.y);
                const float2 a2 = __half22float2(*(const __half2*)&a4.z);
                const float2 a3 = __half22float2(*(const __half2*)&a4.w);
                const float4 c0 = *(const float4*)(sC + k0 + q * 8);
                const float4 c1 = *(const float4*)(sC + k0 + q * 8 + 4);
                uint4 u;
                u.x = gelu2t_h2(a0.x + c0.x, a0.y + c0.y);
                u.y = gelu2t_h2(a1.x + c0.z, a1.y + c0.w);
                u.z = gelu2t_h2(a2.x + c1.x, a2.y + c1.y);
                u.w = gelu2t_h2(a3.x + c1.z, a3.y + c1.w);
                *(uint4*)(uDst + q * 8) = u;
            }
            #pragma unroll
            for (int i = 0; i < 2; i++) {
                const int e = tid + i * 512;
                const int j = e >> 3, q = e & 7;
                *(uint4*)(wDst + j * US + q * 8) =
                    *(const uint4*)(g_W2h + j * C_ + k0 + q * 8);
            }
        }
        __syncthreads();
    }

    // Epilogue: v = gelu_tanh(acc + b2), w = v @ W3, reduce.
    #pragma unroll
    for (int mi = 0; mi < 2; mi++) {
        float p00 = 0.f, p01 = 0.f, p10 = 0.f, p11 = 0.f;
        #pragma unroll
        for (int ni = 0; ni < 4; ni++) {
            const int jb = wn * 32 + ni * 8 + tig * 2;
            float v0, v1, v2, v3;
            gelu2t_f(acc[mi][ni][0] + sB2[jb], acc[mi][ni][1] + sB2[jb + 1], v0, v1);
            gelu2t_f(acc[mi][ni][2] + sB2[jb], acc[mi][ni][3] + sB2[jb + 1], v2, v3);
            p00 += v0 * sW3[2 * jb]     + v1 * sW3[2 * jb + 2];
            p01 += v0 * sW3[2 * jb + 1] + v1 * sW3[2 * jb + 3];
            p10 += v2 * sW3[2 * jb]     + v3 * sW3[2 * jb + 2];
            p11 += v2 * sW3[2 * jb + 1] + v3 * sW3[2 * jb + 3];
        }
        #pragma unroll
        for (int o = 1; o < 4; o <<= 1) {
            p00 += __shfl_xor_sync(0xffffffffu, p00, o);
            p01 += __shfl_xor_sync(0xffffffffu, p01, o);
            p10 += __shfl_xor_sync(0xffffffffu, p10, o);
            p11 += __shfl_xor_sync(0xffffffffu, p11, o);
        }
        if (tig == 0) {
            const int r0 = wm * 32 + mi * 16 + g;
            sPW[wn][r0][0] = p00;  sPW[wn][r0][1] = p01;
            sPW[wn][r0 + 8][0] = p10;  sPW[wn][r0 + 8][1] = p11;
        }
    }
    __syncthreads();

    if (tid < HALF_) {
        float w0 = b3[0], w1 = b3[1];
        #pragma unroll
        for (int w = 0; w < 4; w++) {
            w0 += sPW[w][tid][0];
            w1 += sPW[w][tid][1];
        }
        const float m = fmaxf(w0, w1);
        const float l = m + logf(expf(w0 - m) + expf(w1 - m));
        const int t = t0 + tid;
        const long long o0 = ((long long)bi * N_ + t) * 2;
        out[o0]     = w0 - l;
        out[o0 + 1] = w1 - l;
    }
}

// ---------------------------------------------------------------------------
extern "C" void kernel_launch(void* const* d_in, const int* in_sizes, int n_in,
                              void* d_out, int out_size)
{
    const float* x      = (const float*)d_in[0];
    const float* query  = (const float*)d_in[1];
    const float* policy = (const float*)d_in[2];
    const float* ln_g   = (const float*)d_in[3];
    const float* ln_b   = (const float*)d_in[4];
    const float* W_in   = (const float*)d_in[5];
    const float* b_in   = (const float*)d_in[6];
    const float* W1     = (const float*)d_in[7];
    const float* b1     = (const float*)d_in[8];
    const float* W2     = (const float*)d_in[9];
    const float* b2     = (const float*)d_in[10];
    const float* W3     = (const float*)d_in[11];
    const float* b3     = (const float*)d_in[12];
    float* out = (float*)d_out;

    const int dyn_bytes = 4 * UBUF * (int)sizeof(__half);  // 73728
    cudaFuncSetAttribute(k4_h16, cudaFuncAttributeMaxDynamicSharedMemorySize,
                         dyn_bytes);

    k1_ln_gemm_gelu<<<256 + B_ * NQ_, 1024>>>(x, ln_g, ln_b, W_in, b_in, W1, query);
    k23_pre<<<18, 512>>>(W1, policy, b1, W2);
    k4_h16<<<dim3(N_ / 128, B_ * NQ_), 512, dyn_bytes>>>(b2, W3, b3, out);
}

// round 17
// speedup vs baseline: 1.0814x; 1.0814x over previous
#include <cuda_runtime.h>
#include <math.h>
#include <stdint.h>
#include <cuda_fp16.h>

// Problem dims (fixed by the dataset)
#define B_  2
#define N_  1024
#define C_  256
#define NQ_ 100
#define HALF_ 128

// Scratch (device globals: no allocation allowed)
__device__ __half g_Ah[B_ * N_ * C_];      // h_loc @ W1a (fp16)   (per b,t)
__device__ float  g_hg[B_ * N_ * HALF_];   // h glob half          (per b,t)
__device__ float  g_Cq[B_ * NQ_ * C_];     // q@W1c                (per b,i)
__device__ float  g_gt[B_ * C_];           // glob@W1b + b1        (per b)
__device__ __half g_W2h[HALF_ * C_];       // W2 transposed [j][k], fp16

// ---------------------------------------------------------------------------
// gelu, packed helpers (f32x2, sm_100+ PTX)
// ---------------------------------------------------------------------------
__device__ __forceinline__ uint64_t dup2_(float c) {
    uint64_t r; asm("mov.b64 %0, {%1, %1};" : "=l"(r) : "f"(c)); return r;
}
#define FMA2_(d, a, b, c) asm("fma.rn.f32x2 %0, %1, %2, %3;" : "=l"(d) : "l"(a), "l"(b), "l"(c))
#define MUL2_(d, a, b)    asm("mul.rn.f32x2 %0, %1, %2;"     : "=l"(d) : "l"(a), "l"(b))
#define ADD2_(d, a, b)    asm("add.rn.f32x2 %0, %1, %2;"     : "=l"(d) : "l"(a), "l"(b))

// Exact-precision path: A-S 7.1.26 erf (|err|<=1.5e-7), packed 2-wide.
__device__ __forceinline__ void gelu2_f(float xa, float xb, float& ra, float& rb) {
    uint64_t xp; asm("mov.b64 %0, {%1, %2};" : "=l"(xp) : "f"(xa), "f"(xb));
    const uint64_t ap = xp & 0x7FFFFFFF7FFFFFFFULL;
    uint64_t axk; MUL2_(axk, ap, dup2_(0.70710678118654752440f));
    uint64_t den; FMA2_(den, axk, dup2_(0.3275911f), dup2_(1.0f));
    float d0, d1; asm("mov.b64 {%0, %1}, %2;" : "=f"(d0), "=f"(d1) : "l"(den));
    float t0, t1;
    asm("rcp.approx.f32 %0, %1;" : "=f"(t0) : "f"(d0));
    asm("rcp.approx.f32 %0, %1;" : "=f"(t1) : "f"(d1));
    uint64_t t; asm("mov.b64 %0, {%1, %2};" : "=l"(t) : "f"(t0), "f"(t1));
    uint64_t p;
    FMA2_(p, dup2_(1.061405429f), t, dup2_(-1.453152027f));
    FMA2_(p, p, t, dup2_(1.421413741f));
    FMA2_(p, p, t, dup2_(-0.284496736f));
    FMA2_(p, p, t, dup2_(0.254829592f));
    MUL2_(p, p, t);
    uint64_t z2; MUL2_(z2, axk, axk);
    uint64_t w;  MUL2_(w, z2, dup2_(-1.4426950408889634f));   // -z^2 * log2(e)
    float w0, w1; asm("mov.b64 {%0, %1}, %2;" : "=f"(w0), "=f"(w1) : "l"(w));
    float e0, e1;
    asm("ex2.approx.f32 %0, %1;" : "=f"(e0) : "f"(w0));
    asm("ex2.approx.f32 %0, %1;" : "=f"(e1) : "f"(w1));
    uint64_t e; asm("mov.b64 %0, {%1, %2};" : "=l"(e) : "f"(e0), "f"(e1));
    uint64_t pe; MUL2_(pe, p, e);
    uint64_t er; FMA2_(er, pe, dup2_(-1.0f), dup2_(1.0f));    // 1 - p*e = erf(ax)
    const uint64_t s = er | (xp & 0x8000000080000000ULL);     // copysign (er>0)
    uint64_t onep; ADD2_(onep, s, dup2_(1.0f));
    uint64_t hx;   MUL2_(hx, xp, dup2_(0.5f));
    uint64_t res;  MUL2_(res, onep, hx);
    asm("mov.b64 {%0, %1}, %2;" : "=f"(ra), "=f"(rb) : "l"(res));
}

__device__ __forceinline__ uint32_t f2h2(float a, float b) {
    __half2 h = __floats2half2_rn(a, b);
    return *reinterpret_cast<uint32_t*>(&h);
}

// Fast path: tanh-form gelu with HW tanh.approx (floats out).
__device__ __forceinline__ void gelu2t_f(float xa, float xb, float& ra, float& rb) {
    uint64_t xp; asm("mov.b64 %0, {%1, %2};" : "=l"(xp) : "f"(xa), "f"(xb));
    uint64_t z2; MUL2_(z2, xp, xp);
    uint64_t cc; FMA2_(cc, z2, dup2_(0.0356774081f), dup2_(0.7978845608f));
    uint64_t in; MUL2_(in, xp, cc);
    float i0, i1; asm("mov.b64 {%0, %1}, %2;" : "=f"(i0), "=f"(i1) : "l"(in));
    float t0, t1;
    asm("tanh.approx.f32 %0, %1;" : "=f"(t0) : "f"(i0));
    asm("tanh.approx.f32 %0, %1;" : "=f"(t1) : "f"(i1));
    uint64_t tp; asm("mov.b64 %0, {%1, %2};" : "=l"(tp) : "f"(t0), "f"(t1));
    uint64_t hf; FMA2_(hf, tp, dup2_(0.5f), dup2_(0.5f));
    uint64_t res; MUL2_(res, xp, hf);
    asm("mov.b64 {%0, %1}, %2;" : "=f"(ra), "=f"(rb) : "l"(res));
}

__device__ __forceinline__ uint32_t gelu2t_h2(float xa, float xb) {
    float ra, rb;
    gelu2t_f(xa, xb, ra, rb);
    return f2h2(ra, rb);
}

__device__ __forceinline__ void mma_f16(float* d, const uint32_t* a, const uint32_t* b) {
    asm volatile(
        "mma.sync.aligned.m16n8k16.row.col.f32.f16.f16.f32 "
        "{%0,%1,%2,%3}, {%4,%5,%6,%7}, {%8,%9}, {%0,%1,%2,%3};"
        : "+f"(d[0]), "+f"(d[1]), "+f"(d[2]), "+f"(d[3])
        : "r"(a[0]), "r"(a[1]), "r"(a[2]), "r"(a[3]), "r"(b[0]), "r"(b[1]));
}

// ---------------------------------------------------------------------------
// K1 (merged): blocks 0..255   : h = gelu(LN(x)@W_in+b_in); A_loc = h_loc@W1a
//              blocks 256..455 : Cq[b,i,:] = query[i,b,:] @ W1[256:512]
// 1024 threads, 4-way split-K: thread = (col, kq). Combine phases distributed
// across all 4 kq groups (each owns 2 rows).
// ---------------------------------------------------------------------------
__global__ void __launch_bounds__(1024) k1_ln_gemm_gelu(
    const float* __restrict__ x, const float* __restrict__ ln_g,
    const float* __restrict__ ln_b, const float* __restrict__ Win,
    const float* __restrict__ bin, const float* __restrict__ W1,
    const float* __restrict__ query)
{
    const int blk = blockIdx.x;
    const int tid = threadIdx.x;
    const int col = tid & 255;
    const int kq  = tid >> 8;            // 0..3

    if (blk >= 256) {
        // ---- query GEMM: one CTA per (b,i) ----
        __shared__ float sQ[C_];
        __shared__ float pq[3][C_];
        const int bi = blk - 256;
        const int b = bi / NQ_, i = bi % NQ_;
        if (tid < C_) sQ[tid] = query[(i * B_ + b) * C_ + tid];
        __syncthreads();

        float a[8];
        #pragma unroll
        for (int u = 0; u < 8; u++) a[u] = 0.f;
        const int kb = kq * 64;
        #pragma unroll 2
        for (int k = kb; k < kb + 64; k += 8) {
            #pragma unroll
            for (int u = 0; u < 8; u++)
                a[u] += sQ[k + u] * W1[(C_ + k + u) * C_ + col];
        }
        const float sum =
            ((a[0] + a[1]) + (a[2] + a[3])) + ((a[4] + a[5]) + (a[6] + a[7]));
        if (kq > 0) pq[kq - 1][col] = sum;
        __syncthreads();
        if (kq == 0)
            g_Cq[bi * C_ + col] = sum + pq[0][col] + pq[1][col] + pq[2][col];
        return;
    }

    __shared__ __align__(16) float sY[8][C_];
    __shared__ float pp[4][8][C_];
    __shared__ float sred[8][8][2];
    __shared__ float smu[8], ssc[8];

    const int lane = tid & 31;
    const int wid  = tid >> 5;           // 0..31
    const int row0 = blk * 8;

    const float gv = ln_g[col];
    const float bv = ln_b[col];

    // --- stats: quarter kq owns rows kq*2, kq*2+1 ---
    const int rbase = kq * 2;
    float xv[2];
    #pragma unroll
    for (int r = 0; r < 2; r++)
        xv[r] = x[(row0 + rbase + r) * C_ + col];

    {
        const int w8 = wid & 7;
        #pragma unroll
        for (int r = 0; r < 2; r++) {
            float s = xv[r], q = xv[r] * xv[r];
            #pragma unroll
            for (int o = 16; o; o >>= 1) {
                s += __shfl_xor_sync(0xffffffffu, s, o);
                q += __shfl_xor_sync(0xffffffffu, q, o);
            }
            if (lane == 0) { sred[rbase + r][w8][0] = s; sred[rbase + r][w8][1] = q; }
        }
    }
    __syncthreads();
    if (wid < 8) {
        float s = (lane < 8) ? sred[wid][lane][0] : 0.f;
        float q = (lane < 8) ? sred[wid][lane][1] : 0.f;
        #pragma unroll
        for (int o = 4; o; o >>= 1) {
            s += __shfl_xor_sync(0xffffffffu, s, o);
            q += __shfl_xor_sync(0xffffffffu, q, o);
        }
        if (lane == 0) {
            const float mu = s * (1.0f / C_);
            const float var = q * (1.0f / C_) - mu * mu;
            smu[wid] = mu;
            ssc[wid] = rsqrtf(var + 1e-5f);
        }
    }
    __syncthreads();
    #pragma unroll
    for (int r = 0; r < 2; r++)
        sY[rbase + r][col] = (xv[r] - smu[rbase + r]) * ssc[rbase + r] * gv + bv;
    __syncthreads();

    // --- GEMM1: y @ W_in, K=256 split 64/64/64/64 across kq ---
    float acc[8];
    #pragma unroll
    for (int r = 0; r < 8; r++) acc[r] = 0.f;
    {
        const int kb = kq * 64;
        for (int k = kb; k < kb + 64; k += 4) {
            const float w0 = Win[(k + 0) * C_ + col];
            const float w1 = Win[(k + 1) * C_ + col];
            const float w2 = Win[(k + 2) * C_ + col];
            const float w3 = Win[(k + 3) * C_ + col];
            #pragma unroll
            for (int r = 0; r < 8; r++) {
                const float4 y = *(const float4*)&sY[r][k];
                acc[r] += y.x * w0 + y.y * w1 + y.z * w2 + y.w * w3;
            }
        }
    }
    #pragma unroll
    for (int r = 0; r < 8; r++) pp[kq][r][col] = acc[r];
    __syncthreads();

    // --- combine + gelu + store: each kq group owns rows kq*2, kq*2+1 ---
    {
        const float bi0 = bin[col];
        const int r0 = rbase;
        const float s0 = (pp[0][r0][col] + pp[1][r0][col])
                       + (pp[2][r0][col] + pp[3][r0][col]) + bi0;
        const float s1 = (pp[0][r0 + 1][col] + pp[1][r0 + 1][col])
                       + (pp[2][r0 + 1][col] + pp[3][r0 + 1][col]) + bi0;
        float h0, h1;
        gelu2_f(s0, s1, h0, h1);
        if (col < HALF_) {
            sY[r0][col] = h0;
            sY[r0 + 1][col] = h1;
        } else {
            g_hg[(row0 + r0) * HALF_ + col - HALF_] = h0;
            g_hg[(row0 + r0 + 1) * HALF_ + col - HALF_] = h1;
        }
    }
    __syncthreads();

    // --- GEMM2: h_loc @ W1[0:128], K=128 split 32x4 across kq ---
    float a2[8];
    #pragma unroll
    for (int r = 0; r < 8; r++) a2[r] = 0.f;
    {
        const int kb = kq * 32;
        for (int k = kb; k < kb + 32; k += 4) {
            const float w0 = W1[(k + 0) * C_ + col];
            const float w1 = W1[(k + 1) * C_ + col];
            const float w2 = W1[(k + 2) * C_ + col];
            const float w3 = W1[(k + 3) * C_ + col];
            #pragma unroll
            for (int r = 0; r < 8; r++) {
                const float4 y = *(const float4*)&sY[r][k];
                a2[r] += y.x * w0 + y.y * w1 + y.z * w2 + y.w * w3;
            }
        }
    }
    #pragma unroll
    for (int r = 0; r < 8; r++) pp[kq][r][col] = a2[r];
    __syncthreads();
    {
        #pragma unroll
        for (int rr = 0; rr < 2; rr++) {
            const int r = rbase + rr;
            const float s = (pp[0][r][col] + pp[1][r][col])
                          + (pp[2][r][col] + pp[3][r][col]);
            g_Ah[(row0 + r) * C_ + col] = __float2half_rn(s);
        }
    }
}

// ---------------------------------------------------------------------------
// K23: remaining prologue.  grid = 18 CTAs x 512 thr.
//   blocks 0..1   : glob + gt (needs g_hg from k1)
//   blocks 2..17  : W2h transpose to fp16
// ---------------------------------------------------------------------------
__global__ void __launch_bounds__(512) k23_pre(
    const float* __restrict__ W1, const float* __restrict__ policy,
    const float* __restrict__ b1, const float* __restrict__ W2)
{
    const int blk = blockIdx.x;
    const int tid = threadIdx.x;

    if (blk < 2) {
        const int b = blk;
        const int lane = tid & 31, wid = tid >> 5;
        __shared__ float spol[N_];
        __shared__ float sred[16];
        __shared__ float sps;
        __shared__ float sG[4][HALF_];
        __shared__ float sglob[HALF_];

        float ps = 0.f;
        #pragma unroll
        for (int i = 0; i < 2; i++) {
            const float p = policy[b * N_ + tid + i * 512];
            spol[tid + i * 512] = p;
            ps += p;
        }
        #pragma unroll
        for (int o = 16; o; o >>= 1) ps += __shfl_xor_sync(0xffffffffu, ps, o);
        if (lane == 0) sred[wid] = ps;
        __syncthreads();

        const int c = tid & 127, sl = tid >> 7;     // 4 slices of 256 t
        float acc = 0.f;
        for (int t = sl * 256; t < sl * 256 + 256; t++)
            acc += g_hg[(b * N_ + t) * HALF_ + c] * spol[t];
        sG[sl][c] = acc;
        if (tid == 0) {
            float s = 0.f;
            #pragma unroll
            for (int w = 0; w < 16; w++) s += sred[w];
            sps = s;
        }
        __syncthreads();
        if (tid < HALF_)
            sglob[tid] = (sG[0][tid] + sG[1][tid] + sG[2][tid] + sG[3][tid]) / sps;
        __syncthreads();

        if (tid < C_) {
            float g = b1[tid];
            for (int k = 0; k < HALF_; k++)
                g += sglob[k] * W1[(HALF_ + k) * C_ + tid];
            g_gt[b * C_ + tid] = g;
        }
    } else {
        const int base = (blk - 2) * 2048;
        #pragma unroll
        for (int i = 0; i < 4; i++) {
            const int lin = base + i * 512 + tid;   // index into W2 [k][j]
            const int k = lin >> 7, j = lin & 127;
            g_W2h[j * C_ + k] = __float2half_rn(W2[lin]);
        }
    }
}

// ---------------------------------------------------------------------------
// K4: fused  u = gelu(Aloc[b,t]+Cq[b,i]+gt[b]) ; v = gelu(u@W2+b2) ;
//            w = v@W3+b3 ; out = log_softmax(w)
// fp16 mma.sync m16n8k16, fp32 accum. Double-buffered K-chunks of 64.
// grid (8, 200), 256 threads = 8 warps (2x4 warp tile over 128x128).
// (Proven 101.1us configuration - do not perturb.)
// ---------------------------------------------------------------------------
#define KC  64                 // K elements per chunk
#define US  72                 // smem row stride in halves (pad 8)
#define UBUF (128 * US)        // halves per buffer

__global__ void __launch_bounds__(256, 2) k4_h16(
    const float* __restrict__ b2v,
    const float* __restrict__ W3, const float* __restrict__ b3,
    float* __restrict__ out)
{
    extern __shared__ __half dynh[];
    __half* sU = dynh;                  // [2][128*US] gelu tile (fp16)
    __half* sW = dynh + 2 * UBUF;       // [2][128*US] W2 chunk  (fp16)

    __shared__ __align__(16) float sC[C_];
    __shared__ float sB2[HALF_];
    __shared__ float sW3[2 * HALF_];
    __shared__ float sPW[4][HALF_][2];

    const int tid = threadIdx.x;
    const int lane = tid & 31, warp = tid >> 5;
    const int wm = warp >> 2, wn = warp & 3;  // 2x4 warp grid
    const int g = lane >> 2, tig = lane & 3;

    const int bi = blockIdx.y;            // b*100 + i
    const int b = bi / NQ_;
    const int t0 = blockIdx.x * 128;
    const __half* aBase = g_Ah + (b * N_ + t0) * C_;

    sC[tid] = g_Cq[bi * C_ + tid] + g_gt[b * C_ + tid];
    if (tid < HALF_) sB2[tid] = b2v[tid];
    sW3[tid] = W3[tid];

    float acc[4][4][4];
    #pragma unroll
    for (int mi = 0; mi < 4; mi++)
        #pragma unroll
        for (int ni = 0; ni < 4; ni++)
            #pragma unroll
            for (int q = 0; q < 4; q++) acc[mi][ni][q] = 0.f;
    __syncthreads();   // sC ready before first fill

    // fill chunk 0 into buffer 0
    {
        __half* uDst = sU;
        __half* wDst = sW;
        #pragma unroll
        for (int i = 0; i < 4; i++) {
            const int e = tid + i * 256;
            const int t = e >> 3, q = e & 7;       // q: 8-half group in [0,64)
            const uint4 a4 = *(const uint4*)(aBase + t * C_ + q * 8);
            const float2 a0 = __half22float2(*(const __half2*)&a4.x);
            const float2 a1 = __half22float2(*(const __half2*)&a4.y);
            const float2 a2 = __half22float2(*(const __half2*)&a4.z);
            const float2 a3 = __half22float2(*(const __half2*)&a4.w);
            const float4 c0 = *(const float4*)(sC + q * 8);
            const float4 c1 = *(const float4*)(sC + q * 8 + 4);
            uint4 u;
            u.x = gelu2t_h2(a0.x + c0.x, a0.y + c0.y);
            u.y = gelu2t_h2(a1.x + c0.z, a1.y + c0.w);
            u.z = gelu2t_h2(a2.x + c1.x, a2.y + c1.y);
            u.w = gelu2t_h2(a3.x + c1.z, a3.y + c1.w);
            *(uint4*)(uDst + t * US + q * 8) = u;
        }
        #pragma unroll
        for (int i = 0; i < 4; i++) {
            const int e = tid + i * 256;
            const int j = e >> 3, q = e & 7;
            *(uint4*)(wDst + j * US + q * 8) =
                *(const uint4*)(g_W2h + j * C_ + q * 8);
        }
    }
    __syncthreads();

    for (int c = 0; c < 4; c++) {
        const __half* bU = sU + (c & 1) * UBUF;
        const __half* bW = sW + (c & 1) * UBUF;

        #pragma unroll
        for (int ks = 0; ks < KC; ks += 16) {
            uint32_t af[4][4], bf[4][2];
            #pragma unroll
            for (int mi = 0; mi < 4; mi++) {
                const int row = wm * 64 + mi * 16 + g;
                af[mi][0] = *(const uint32_t*)(bU + row * US + ks + 2 * tig);
                af[mi][1] = *(const uint32_t*)(bU + (row + 8) * US + ks + 2 * tig);
                af[mi][2] = *(const uint32_t*)(bU + row * US + ks + 2 * tig + 8);
                af[mi][3] = *(const uint32_t*)(bU + (row + 8) * US + ks + 2 * tig + 8);
            }
            #pragma unroll
            for (int ni = 0; ni < 4; ni++) {
                const int j = wn * 32 + ni * 8 + g;
                bf[ni][0] = *(const uint32_t*)(bW + j * US + ks + 2 * tig);
                bf[ni][1] = *(const uint32_t*)(bW + j * US + ks + 2 * tig + 8);
            }
            #pragma unroll
            for (int mi = 0; mi < 4; mi++)
                #pragma unroll
                for (int ni = 0; ni < 4; ni++)
                    mma_f16(acc[mi][ni], af[mi], bf[ni]);
        }

        if (c < 3) {
            const int k0 = (c + 1) * KC;
            __half* uDst = sU + ((c + 1) & 1) * UBUF;
            __half* wDst = sW + ((c + 1) & 1) * UBUF;
            #pragma unroll
            for (int i = 0; i < 4; i++) {
                const int e = tid + i * 256;
                const int t = e >> 3, q = e & 7;
                const uint4 a4 = *(const uint4*)(aBase + t * C_ + k0 + q * 8);
                const float2 a0 = __half22float2(*(const __half2*)&a4.x);
                const float2 a1 = __half22float2(*(const __half2*)&a4.y);
                const float2 a2 = __half22float2(*(const __half2*)&a4.z);
                const float2 a3 = __half22float2(*(const __half2*)&a4.w);
                const float4 c0 = *(const float4*)(sC + k0 + q * 8);
                const float4 c1 = *(const float4*)(sC + k0 + q * 8 + 4);
                uint4 u;
                u.x = gelu2t_h2(a0.x + c0.x, a0.y + c0.y);
                u.y = gelu2t_h2(a1.x + c0.z, a1.y + c0.w);
                u.z = gelu2t_h2(a2.x + c1.x, a2.y + c1.y);
                u.w = gelu2t_h2(a3.x + c1.z, a3.y + c1.w);
                *(uint4*)(uDst + q * 8 + t * US) = u;
            }
            #pragma unroll
            for (int i = 0; i < 4; i++) {
                const int e = tid + i * 256;
                const int j = e >> 3, q = e & 7;
                *(uint4*)(wDst + j * US + q * 8) =
                    *(const uint4*)(g_W2h + j * C_ + k0 + q * 8);
            }
        }
        __syncthreads();
    }

    // Epilogue: v = gelu_tanh(acc + b2), w = v @ W3, reduce.
    #pragma unroll
    for (int mi = 0; mi < 4; mi++) {
        float p00 = 0.f, p01 = 0.f, p10 = 0.f, p11 = 0.f;
        #pragma unroll
        for (int ni = 0; ni < 4; ni++) {
            const int jb = wn * 32 + ni * 8 + tig * 2;
            float v0, v1, v2, v3;
            gelu2t_f(acc[mi][ni][0] + sB2[jb], acc[mi][ni][1] + sB2[jb + 1], v0, v1);
            gelu2t_f(acc[mi][ni][2] + sB2[jb], acc[mi][ni][3] + sB2[jb + 1], v2, v3);
            p00 += v0 * sW3[2 * jb]     + v1 * sW3[2 * jb + 2];
            p01 += v0 * sW3[2 * jb + 1] + v1 * sW3[2 * jb + 3];
            p10 += v2 * sW3[2 * jb]     + v3 * sW3[2 * jb + 2];
            p11 += v2 * sW3[2 * jb + 1] + v3 * sW3[2 * jb + 3];
        }
        #pragma unroll
        for (int o = 1; o < 4; o <<= 1) {
            p00 += __shfl_xor_sync(0xffffffffu, p00, o);
            p01 += __shfl_xor_sync(0xffffffffu, p01, o);
            p10 += __shfl_xor_sync(0xffffffffu, p10, o);
            p11 += __shfl_xor_sync(0xffffffffu, p11, o);
        }
        if (tig == 0) {
            const int r0 = wm * 64 + mi * 16 + g;
            sPW[wn][r0][0] = p00;  sPW[wn][r0][1] = p01;
            sPW[wn][r0 + 8][0] = p10;  sPW[wn][r0 + 8][1] = p11;
        }
    }
    __syncthreads();

    if (tid < HALF_) {
        float w0 = b3[0], w1 = b3[1];
        #pragma unroll
        for (int w = 0; w < 4; w++) {
            w0 += sPW[w][tid][0];
            w1 += sPW[w][tid][1];
        }
        const float m = fmaxf(w0, w1);
        const float l = m + logf(expf(w0 - m) + expf(w1 - m));
        const int t = t0 + tid;
        const long long o0 = ((long long)bi * N_ + t) * 2;
        out[o0]     = w0 - l;
        out[o0 + 1] = w1 - l;
    }
}

// ---------------------------------------------------------------------------
extern "C" void kernel_launch(void* const* d_in, const int* in_sizes, int n_in,
                              void* d_out, int out_size)
{
    const float* x      = (const float*)d_in[0];
    const float* query  = (const float*)d_in[1];
    const float* policy = (const float*)d_in[2];
    const float* ln_g   = (const float*)d_in[3];
    const float* ln_b   = (const float*)d_in[4];
    const float* W_in   = (const float*)d_in[5];
    const float* b_in   = (const float*)d_in[6];
    const float* W1     = (const float*)d_in[7];
    const float* b1     = (const float*)d_in[8];
    const float* W2     = (const float*)d_in[9];
    const float* b2     = (const float*)d_in[10];
    const float* W3     = (const float*)d_in[11];
    const float* b3     = (const float*)d_in[12];
    float* out = (float*)d_out;

    const int dyn_bytes = 4 * UBUF * (int)sizeof(__half);  // 73728
    cudaFuncSetAttribute(k4_h16, cudaFuncAttributeMaxDynamicSharedMemorySize,
                         dyn_bytes);

    k1_ln_gemm_gelu<<<256 + B_ * NQ_, 1024>>>(x, ln_g, ln_b, W_in, b_in, W1, query);
    k23_pre<<<18, 512>>>(W1, policy, b1, W2);
    k4_h16<<<dim3(N_ / 128, B_ * NQ_), 256, dyn_bytes>>>(b2, W3, b3, out);
}